// round 2
// baseline (speedup 1.0000x reference)
#include <cuda_runtime.h>
#include <math.h>

#define BB 16
#define TT 4096
#define DD 512

// ---------------- device scratch (no allocations allowed) ----------------
__device__ float g_w0[DD], g_w1[DD], g_w2[DD], g_gw[DD];
__device__ float g_C0, g_C1;                 // sum(beta*w), sum(gamma*w)
__device__ float g_scale[BB], g_sumalpha[BB];
__device__ int4  g_evi[BB * (TT + 1)];       // (s, e, pos, lead-bits)
__device__ float g_evc[BB * (TT + 1)];       // end coefficient
__device__ int   g_nev[BB];

// ---------------- K_pre: transpose conv weights, reduce constants --------
__global__ void cif_pre(const float* __restrict__ cw,
                        const float* __restrict__ gam,
                        const float* __restrict__ bet,
                        const float* __restrict__ pw) {
    int d = threadIdx.x;  // 512 threads
    float w0 = cw[3 * d + 0], w1 = cw[3 * d + 1], w2 = cw[3 * d + 2];
    g_w0[d] = w0; g_w1[d] = w1; g_w2[d] = w2;
    float gw = gam[d] * pw[d];
    float bw = bet[d] * pw[d];
    g_gw[d] = gw;
    __shared__ float sh1[512], sh2[512];
    sh1[d] = gw; sh2[d] = bw;
    __syncthreads();
    for (int off = 256; off; off >>= 1) {
        if (d < off) { sh1[d] += sh1[d + off]; sh2[d] += sh2[d + off]; }
        __syncthreads();
    }
    if (d == 0) { g_C1 = sh1[0]; g_C0 = sh2[0]; }
}

// ---------------- K_alpha: depthwise conv + LN + sigmoid gate ------------
// one warp per timestep; 3 scalar reductions in a single pass:
//   s1 = sum(y), s2 = sum(y^2), sg = sum(y * gamma * proj_w)
// logit = rs*(sg - mu*C1) + C0 + proj_b,  rs = 1/sqrt(var+1e-5)
__global__ void __launch_bounds__(256)
cif_alpha(const float* __restrict__ enc, const int* __restrict__ ilen,
          const float* __restrict__ projb, float* __restrict__ alpha) {
    int b = blockIdx.y;
    int warp = threadIdx.x >> 5, lane = threadIdx.x & 31;
    int len = __ldg(&ilen[b]);
    float pb = __ldg(projb);
    const float* base = enc + (size_t)b * TT * DD;
    float C0 = g_C0, C1 = g_C1;
    int t0 = blockIdx.x * 64 + warp * 8;

    for (int i = 0; i < 8; i++) {
        int t = t0 + i;
        float s1 = 0.f, s2 = 0.f, sg = 0.f;
#pragma unroll
        for (int j = 0; j < 4; j++) {
            int d = j * 128 + lane * 4;
            float4 w0 = *(const float4*)(g_w0 + d);
            float4 w1 = *(const float4*)(g_w1 + d);
            float4 w2 = *(const float4*)(g_w2 + d);
            float4 gw = *(const float4*)(g_gw + d);
            const float* p = base + (size_t)t * DD + d;
            float4 cur = *(const float4*)(p);
            float4 prv = make_float4(0.f, 0.f, 0.f, 0.f);
            float4 nxt = make_float4(0.f, 0.f, 0.f, 0.f);
            if (t > 0)      prv = *(const float4*)(p - DD);
            if (t < TT - 1) nxt = *(const float4*)(p + DD);
            float yx = w0.x * prv.x + w1.x * cur.x + w2.x * nxt.x;
            float yy = w0.y * prv.y + w1.y * cur.y + w2.y * nxt.y;
            float yz = w0.z * prv.z + w1.z * cur.z + w2.z * nxt.z;
            float yw = w0.w * prv.w + w1.w * cur.w + w2.w * nxt.w;
            s1 += yx + yy + yz + yw;
            s2 += yx * yx + yy * yy + yz * yz + yw * yw;
            sg += yx * gw.x + yy * gw.y + yz * gw.z + yw * gw.w;
        }
#pragma unroll
        for (int off = 16; off; off >>= 1) {
            s1 += __shfl_xor_sync(0xffffffffu, s1, off);
            s2 += __shfl_xor_sync(0xffffffffu, s2, off);
            sg += __shfl_xor_sync(0xffffffffu, sg, off);
        }
        if (lane == 0) {
            float mu  = s1 * (1.0f / DD);
            float var = s2 * (1.0f / DD) - mu * mu;
            float rs  = 1.0f / sqrtf(var + 1e-5f);
            float logit = rs * (sg - mu * C1) + C0 + pb;
            float a = 1.0f / (1.0f + expf(-logit));
            if (t >= len) a = 0.f;
            alpha[(size_t)b * TT + t] = a;
        }
    }
}

// ---------------- K_reduce: per-batch sum(alpha), rescale factor ---------
__global__ void cif_reduce(const float* __restrict__ alpha,
                           const int* __restrict__ tlen) {
    int b = blockIdx.x;
    float p = 0.f;
    for (int t = threadIdx.x; t < TT; t += blockDim.x)
        p += alpha[(size_t)b * TT + t];
    __shared__ float sh[256];
    sh[threadIdx.x] = p;
    __syncthreads();
    for (int off = 128; off; off >>= 1) {
        if (threadIdx.x < off) sh[threadIdx.x] += sh[threadIdx.x + off];
        __syncthreads();
    }
    if (threadIdx.x == 0) {
        float s = sh[0];
        g_sumalpha[b] = s;
        g_scale[b] = ((float)__ldg(&tlen[b])) / fmaxf(s, 1e-8f);
    }
}

// ---------------- K_qty: quantity loss -----------------------------------
__global__ void cif_qty(const int* __restrict__ tlen, float* __restrict__ qty) {
    int i = threadIdx.x;
    float v = (i < BB) ? fabsf(g_sumalpha[i] - (float)__ldg(&tlen[i])) : 0.f;
#pragma unroll
    for (int off = 16; off; off >>= 1) v += __shfl_xor_sync(0xffffffffu, v, off);
    if (i == 0) *qty = v * (1.0f / BB);
}

// ---------------- K_scan: serial CIF scalar scan, emit fire events -------
// Faithful replication of reference recurrence (incl. clip edge cases).
// Event semantics for the gather:
//   s < e : emb = lead*h[s] + sum_{s<t<e} (alpha[t]*scale)*h[t] + endc*h[e]
//   s == e: emb = endc*h[s]
__global__ void cif_scan(const float* __restrict__ alpha,
                         const int* __restrict__ ilen) {
    int b = threadIdx.x;
    if (b >= BB) return;
    const float* al = alpha + (size_t)b * TT;
    float scale = g_scale[b];
    int len = __ldg(&ilen[b]);
    int4*  evi = g_evi + b * (TT + 1);
    float* evc = g_evc + b * (TT + 1);

    float acc = 0.f, P = 0.f;
    int s = 0, fidx = 0, nev = 0;

    for (int t = 0; t < TT; t++) {
        float a  = __ldg(&al[t]) * scale;
        float na = acc + a;
        if (na >= 1.0f) {                      // fired
            float rem = fmaxf(1.0f - acc, 0.f);
            float ovf = fmaxf(a - rem, 0.f);
            if (fidx < TT) {
                evi[nev] = make_int4(s, t, fidx, __float_as_int(P));
                evc[nev] = rem;                // s==e only at t==0 (wsum=0), endc=rem correct
                nev++; fidx++;
            }
            acc = ovf; s = t; P = ovf;
        } else {
            acc = na;
            if (t == 0) P = a;                 // first segment lead = a_0
        }
    }
    // tail fire: emb = wsum (no rem term). Clamp end to last valid step
    // (alpha is exactly 0 beyond len, contributes 0*h == 0).
    if (acc > 0.5f && fidx < TT) {
        int e = len - 1;
        if (e < s) e = s;
        float endc = (e == s) ? P : __ldg(&al[e]) * scale;
        evi[nev] = make_int4(s, e, fidx, __float_as_int(P));
        evc[nev] = endc;
        nev++;
    }
    g_nev[b] = nev;
}

// ---------------- K_gather: one block per event, segmented weighted sum --
__global__ void __launch_bounds__(128)
cif_gather(const float* __restrict__ enc, const float* __restrict__ alpha,
           float* __restrict__ out) {
    int b = blockIdx.x;
    int nev = g_nev[b];
    float scale = g_scale[b];
    const float*  al = alpha + (size_t)b * TT;
    const float4* eb = (const float4*)(enc + (size_t)b * TT * DD);
    int tid = threadIdx.x;  // 128 threads x float4 = 512 channels

    for (int n = blockIdx.y; n < nev; n += gridDim.y) {
        int4  r    = g_evi[b * (TT + 1) + n];
        float endc = g_evc[b * (TT + 1) + n];
        int s = r.x, e = r.y, pos = r.z;
        float lead = __int_as_float(r.w);

        float4 hs = eb[(size_t)s * (DD / 4) + tid];
        float4 acc;
        if (s == e) {
            acc.x = endc * hs.x; acc.y = endc * hs.y;
            acc.z = endc * hs.z; acc.w = endc * hs.w;
        } else {
            float4 he = eb[(size_t)e * (DD / 4) + tid];
            acc.x = lead * hs.x + endc * he.x;
            acc.y = lead * hs.y + endc * he.y;
            acc.z = lead * hs.z + endc * he.z;
            acc.w = lead * hs.w + endc * he.w;
            for (int t = s + 1; t < e; t++) {
                float  c = __ldg(&al[t]) * scale;
                float4 h = eb[(size_t)t * (DD / 4) + tid];
                acc.x += c * h.x; acc.y += c * h.y;
                acc.z += c * h.z; acc.w += c * h.w;
            }
        }
        float4* ob = (float4*)(out + ((size_t)b * TT + pos) * DD);
        ob[tid] = acc;
    }
}

// ---------------- launcher ------------------------------------------------
extern "C" void kernel_launch(void* const* d_in, const int* in_sizes, int n_in,
                              void* d_out, int out_size) {
    const float* enc   = (const float*)d_in[0];
    const int*   ilen  = (const int*)d_in[1];
    const int*   tlen  = (const int*)d_in[2];
    const float* convw = (const float*)d_in[3];
    const float* gam   = (const float*)d_in[4];
    const float* bet   = (const float*)d_in[5];
    const float* projw = (const float*)d_in[6];
    const float* projb = (const float*)d_in[7];

    float* out   = (float*)d_out;
    float* alpha = out + (size_t)BB * TT * DD;
    float* qty   = alpha + (size_t)BB * TT;

    cudaMemsetAsync(out, 0, (size_t)BB * TT * DD * sizeof(float), 0);
    cif_pre<<<1, 512>>>(convw, gam, bet, projw);
    cif_alpha<<<dim3(TT / 64, BB), 256>>>(enc, ilen, projb, alpha);
    cif_reduce<<<BB, 256>>>(alpha, tlen);
    cif_qty<<<1, 32>>>(tlen, qty);
    cif_scan<<<1, 32>>>(alpha, ilen);
    cif_gather<<<dim3(BB, 128), 128>>>(enc, alpha, out);
}

// round 3
// speedup vs baseline: 2.5018x; 2.5018x over previous
#include <cuda_runtime.h>
#include <math.h>

#define BB 16
#define TT 4096
#define DD 512

// ---------------- device scratch (no allocations allowed) ----------------
__device__ float g_w0[DD], g_w1[DD], g_w2[DD], g_gw[DD];
__device__ float g_C0, g_C1;                 // sum(beta*w), sum(gamma*w)
__device__ float g_scale[BB], g_sumalpha[BB];
__device__ int4  g_evi[BB * (TT + 1)];       // (s, e, pos, lead-bits)
__device__ float g_evc[BB * (TT + 1)];       // end coefficient
__device__ int   g_nev[BB];

// ---------------- K_pre: transpose conv weights, reduce constants --------
__global__ void cif_pre(const float* __restrict__ cw,
                        const float* __restrict__ gam,
                        const float* __restrict__ bet,
                        const float* __restrict__ pw) {
    int d = threadIdx.x;  // 512 threads
    float w0 = cw[3 * d + 0], w1 = cw[3 * d + 1], w2 = cw[3 * d + 2];
    g_w0[d] = w0; g_w1[d] = w1; g_w2[d] = w2;
    float gw = gam[d] * pw[d];
    float bw = bet[d] * pw[d];
    g_gw[d] = gw;
    __shared__ float sh1[512], sh2[512];
    sh1[d] = gw; sh2[d] = bw;
    __syncthreads();
    for (int off = 256; off; off >>= 1) {
        if (d < off) { sh1[d] += sh1[d + off]; sh2[d] += sh2[d + off]; }
        __syncthreads();
    }
    if (d == 0) { g_C1 = sh1[0]; g_C0 = sh2[0]; }
}

// ---------------- K_alpha: depthwise conv + LN + sigmoid gate ------------
// One warp per 8 consecutive timesteps. Rolling prv/cur/nxt registers:
// 10 row-chunk loads per 8 timesteps (was 24). FP accumulation order kept
// identical to the validated R1 kernel (j ascending, same y expression).
__global__ void __launch_bounds__(256)
cif_alpha(const float* __restrict__ enc, const int* __restrict__ ilen,
          const float* __restrict__ projb, float* __restrict__ alpha) {
    int b = blockIdx.y;
    int warp = threadIdx.x >> 5, lane = threadIdx.x & 31;
    int len = __ldg(&ilen[b]);
    float pb = __ldg(projb);
    const float* base = enc + (size_t)b * TT * DD;
    float C0 = g_C0, C1 = g_C1;
    int t0 = blockIdx.x * 64 + warp * 8;

    float s1[8], s2[8], sg[8];
#pragma unroll
    for (int i = 0; i < 8; i++) { s1[i] = 0.f; s2[i] = 0.f; sg[i] = 0.f; }

#pragma unroll
    for (int j = 0; j < 4; j++) {
        int d = j * 128 + lane * 4;
        float4 w0 = *(const float4*)(g_w0 + d);
        float4 w1 = *(const float4*)(g_w1 + d);
        float4 w2 = *(const float4*)(g_w2 + d);
        float4 gw = *(const float4*)(g_gw + d);
        const float* p = base + (size_t)t0 * DD + d;
        float4 prv = make_float4(0.f, 0.f, 0.f, 0.f);
        if (t0 > 0) prv = *(const float4*)(p - DD);
        float4 cur = *(const float4*)(p);
#pragma unroll
        for (int i = 0; i < 8; i++) {
            float4 nxt = make_float4(0.f, 0.f, 0.f, 0.f);
            if (t0 + i < TT - 1) nxt = *(const float4*)(p + (size_t)(i + 1) * DD);
            float yx = w0.x * prv.x + w1.x * cur.x + w2.x * nxt.x;
            float yy = w0.y * prv.y + w1.y * cur.y + w2.y * nxt.y;
            float yz = w0.z * prv.z + w1.z * cur.z + w2.z * nxt.z;
            float yw = w0.w * prv.w + w1.w * cur.w + w2.w * nxt.w;
            s1[i] += yx + yy + yz + yw;
            s2[i] += yx * yx + yy * yy + yz * yz + yw * yw;
            sg[i] += yx * gw.x + yy * gw.y + yz * gw.z + yw * gw.w;
            prv = cur; cur = nxt;
        }
    }

#pragma unroll
    for (int i = 0; i < 8; i++) {
        float a1 = s1[i], a2 = s2[i], a3 = sg[i];
#pragma unroll
        for (int off = 16; off; off >>= 1) {
            a1 += __shfl_xor_sync(0xffffffffu, a1, off);
            a2 += __shfl_xor_sync(0xffffffffu, a2, off);
            a3 += __shfl_xor_sync(0xffffffffu, a3, off);
        }
        if (lane == 0) {
            int t = t0 + i;
            float mu  = a1 * (1.0f / DD);
            float var = a2 * (1.0f / DD) - mu * mu;
            float rs  = 1.0f / sqrtf(var + 1e-5f);
            float logit = rs * (a3 - mu * C1) + C0 + pb;
            float a = 1.0f / (1.0f + expf(-logit));
            if (t >= len) a = 0.f;
            alpha[(size_t)b * TT + t] = a;
        }
    }
}

// ---------------- K_reduce: per-batch sum(alpha), rescale factor ---------
__global__ void cif_reduce(const float* __restrict__ alpha,
                           const int* __restrict__ tlen) {
    int b = blockIdx.x;
    float p = 0.f;
    for (int t = threadIdx.x; t < TT; t += blockDim.x)
        p += alpha[(size_t)b * TT + t];
    __shared__ float sh[256];
    sh[threadIdx.x] = p;
    __syncthreads();
    for (int off = 128; off; off >>= 1) {
        if (threadIdx.x < off) sh[threadIdx.x] += sh[threadIdx.x + off];
        __syncthreads();
    }
    if (threadIdx.x == 0) {
        float s = sh[0];
        g_sumalpha[b] = s;
        g_scale[b] = ((float)__ldg(&tlen[b])) / fmaxf(s, 1e-8f);
    }
}

// ---------------- K_scan: serial CIF scan, one warp per batch ------------
// Only lane 0 runs the scalar recurrence -> fire branch is uniform among
// active threads (no BSSY divergence cost). Alpha is double-buffered 16
// values at a time in registers so loads never sit on the acc chain.
// Block 0 additionally computes the quantity loss.
__global__ void __launch_bounds__(32)
cif_scan(const float* __restrict__ alpha, const int* __restrict__ ilen,
         const int* __restrict__ tlen, float* __restrict__ qty) {
    int b = blockIdx.x;
    int lane = threadIdx.x;

    if (b == 0) {  // quantity loss (all 32 lanes of block 0)
        float v = (lane < BB) ? fabsf(g_sumalpha[lane] - (float)__ldg(&tlen[lane])) : 0.f;
#pragma unroll
        for (int off = 16; off; off >>= 1) v += __shfl_xor_sync(0xffffffffu, v, off);
        if (lane == 0) *qty = v * (1.0f / BB);
    }
    if (lane != 0) return;

    const float4* al4 = (const float4*)(alpha + (size_t)b * TT);
    const float*  al  = alpha + (size_t)b * TT;
    float scale = g_scale[b];
    int len = __ldg(&ilen[b]);
    int4*  evi = g_evi + b * (TT + 1);
    float* evc = g_evc + b * (TT + 1);

    float4 buf[4], nbuf[4];
#pragma unroll
    for (int k = 0; k < 4; k++) buf[k] = __ldg(al4 + k);

    float acc = 0.f;
    float P = buf[0].x * scale;   // lead coeff of first segment if no fire yet
    int s = 0, fidx = 0, nev = 0;

    for (int t0 = 0; t0 < TT; t0 += 16) {
        if (t0 + 16 < TT) {
            int nb = t0 / 4 + 4;
#pragma unroll
            for (int k = 0; k < 4; k++) nbuf[k] = __ldg(al4 + nb + k);
        }
        float av[16];
#pragma unroll
        for (int k = 0; k < 4; k++) {
            av[4 * k + 0] = buf[k].x * scale;
            av[4 * k + 1] = buf[k].y * scale;
            av[4 * k + 2] = buf[k].z * scale;
            av[4 * k + 3] = buf[k].w * scale;
        }
#pragma unroll
        for (int i = 0; i < 16; i++) {
            float a  = av[i];
            float na = acc + a;
            if (na >= 1.0f) {                          // fired (uniform branch)
                float rem = fmaxf(1.0f - acc, 0.0f);
                float ovf = fmaxf(a - rem, 0.0f);
                if (fidx < TT) {
                    evi[nev] = make_int4(s, t0 + i, fidx, __float_as_int(P));
                    evc[nev] = rem;
                    nev++; fidx++;
                }
                s = t0 + i; P = ovf; acc = ovf;
            } else {
                acc = na;
            }
        }
#pragma unroll
        for (int k = 0; k < 4; k++) buf[k] = nbuf[k];
    }
    // tail fire: emb = wsum (no rem term); clamp end to last valid step.
    if (acc > 0.5f && fidx < TT) {
        int e = len - 1;
        if (e < s) e = s;
        float endc = (e == s) ? P : __ldg(&al[e]) * scale;
        evi[nev] = make_int4(s, e, fidx, __float_as_int(P));
        evc[nev] = endc;
        nev++;
    }
    g_nev[b] = nev;
}

// ---------------- K_gather: one block per event, segmented weighted sum --
__global__ void __launch_bounds__(128)
cif_gather(const float* __restrict__ enc, const float* __restrict__ alpha,
           float* __restrict__ out) {
    int b = blockIdx.x;
    int nev = g_nev[b];
    float scale = g_scale[b];
    const float*  al = alpha + (size_t)b * TT;
    const float4* eb = (const float4*)(enc + (size_t)b * TT * DD);
    int tid = threadIdx.x;  // 128 threads x float4 = 512 channels

    for (int n = blockIdx.y; n < nev; n += gridDim.y) {
        int4  r    = g_evi[b * (TT + 1) + n];
        float endc = g_evc[b * (TT + 1) + n];
        int s = r.x, e = r.y, pos = r.z;
        float lead = __int_as_float(r.w);

        float4 hs = eb[(size_t)s * (DD / 4) + tid];
        float4 acc;
        if (s == e) {
            acc.x = endc * hs.x; acc.y = endc * hs.y;
            acc.z = endc * hs.z; acc.w = endc * hs.w;
        } else {
            float4 he = eb[(size_t)e * (DD / 4) + tid];
            acc.x = lead * hs.x + endc * he.x;
            acc.y = lead * hs.y + endc * he.y;
            acc.z = lead * hs.z + endc * he.z;
            acc.w = lead * hs.w + endc * he.w;
            for (int t = s + 1; t < e; t++) {
                float  c = __ldg(&al[t]) * scale;
                float4 h = eb[(size_t)t * (DD / 4) + tid];
                acc.x += c * h.x; acc.y += c * h.y;
                acc.z += c * h.z; acc.w += c * h.w;
            }
        }
        float4* ob = (float4*)(out + ((size_t)b * TT + pos) * DD);
        ob[tid] = acc;
    }
}

// ---------------- launcher ------------------------------------------------
extern "C" void kernel_launch(void* const* d_in, const int* in_sizes, int n_in,
                              void* d_out, int out_size) {
    const float* enc   = (const float*)d_in[0];
    const int*   ilen  = (const int*)d_in[1];
    const int*   tlen  = (const int*)d_in[2];
    const float* convw = (const float*)d_in[3];
    const float* gam   = (const float*)d_in[4];
    const float* bet   = (const float*)d_in[5];
    const float* projw = (const float*)d_in[6];
    const float* projb = (const float*)d_in[7];

    float* out   = (float*)d_out;
    float* alpha = out + (size_t)BB * TT * DD;
    float* qty   = alpha + (size_t)BB * TT;

    cudaMemsetAsync(out, 0, (size_t)BB * TT * DD * sizeof(float), 0);
    cif_pre<<<1, 512>>>(convw, gam, bet, projw);
    cif_alpha<<<dim3(TT / 64, BB), 256>>>(enc, ilen, projb, alpha);
    cif_reduce<<<BB, 256>>>(alpha, tlen);
    cif_scan<<<BB, 32>>>(alpha, ilen, tlen, qty);
    cif_gather<<<dim3(BB, 128), 128>>>(enc, alpha, out);
}